// round 2
// baseline (speedup 1.0000x reference)
#include <cuda_runtime.h>
#include <math.h>

#define HID     256
#define NSTEPS  52
#define BATCH   1024
#define G4      1024          // 4*HID gates per cell
#define KDIM    768           // 512 (input) + 256 (recurrent)

// ---------------- persistent state (device globals; no allocation) ----------
__device__ float g_h[4][BATCH][HID];      // [l0f, l0b, l1f, l1b]
__device__ float g_c[4][BATCH][HID];
__device__ float g_y [BATCH][512];        // layer-0 input (prev step output)
__device__ float g_x1[BATCH][512];        // layer-1 input (concat h0f,h0b)
__device__ float g_gates[2][BATCH][G4];   // per-layer scratch: raw GEMM gates

// ---------------- helpers ---------------------------------------------------
__device__ __forceinline__ unsigned f2tf32(float x) {
    unsigned u;
    asm("cvt.rna.tf32.f32 %0, %1;" : "=r"(u) : "f"(x));
    return u;
}

// ---------------- GEMM: gates[z][b][n] = X_cat[b,:] . W_cat[z][n,:] ---------
// X_cat = [inp(512) | h(256)],  W_cat = [Wih(1024x512) | Whh(1024x256)]
#define BM 128
#define BN 128
#define BK 32
#define LDT 36                 // smem row stride (floats), conflict-free
#define NKT (KDIM / BK)        // 24

__global__ void __launch_bounds__(256, 1)
lstm_gemm(int layer, const float* __restrict__ Wih, const float* __restrict__ Whh)
{
    extern __shared__ unsigned sm[];
    unsigned* As = sm;                   // [2][BM][LDT]
    unsigned* Bs = sm + 2 * BM * LDT;    // [2][BN][LDT]

    const int z = blockIdx.z;                         // direction within layer
    const float* inp  = (layer == 0) ? &g_y[0][0] : &g_x1[0][0];
    const float* hsrc = &g_h[layer * 2 + z][0][0];
    const float* W1 = Wih + (size_t)z * G4 * 512;     // [1024][512]
    const float* W2 = Whh + (size_t)z * G4 * 256;     // [1024][256]

    const int tid  = threadIdx.x;
    const int lane = tid & 31;
    const int warp = tid >> 5;
    const int wm = (warp >> 2) * 64;                  // warp row offset
    const int wn = (warp & 3) * 32;                   // warp col offset
    const int bm = blockIdx.y * BM;
    const int bn = blockIdx.x * BN;

    float acc[4][4][4];
    #pragma unroll
    for (int a = 0; a < 4; a++)
        #pragma unroll
        for (int b = 0; b < 4; b++)
            #pragma unroll
            for (int c = 0; c < 4; c++) acc[a][b][c] = 0.f;

    float4 ra[4], rb[4];

    auto LDG = [&](int kt) {
        const int k0 = kt * BK;
        #pragma unroll
        for (int i = 0; i < 4; i++) {
            int idx = tid + i * 256;
            int row = idx >> 3;
            int c4  = idx & 7;
            int k = k0 + c4 * 4;
            if (k < 512) {
                ra[i] = *(const float4*)(inp + (size_t)(bm + row) * 512 + k);
                rb[i] = *(const float4*)(W1  + (size_t)(bn + row) * 512 + k);
            } else {
                ra[i] = *(const float4*)(hsrc + (size_t)(bm + row) * HID + (k - 512));
                rb[i] = *(const float4*)(W2   + (size_t)(bn + row) * HID + (k - 512));
            }
        }
    };

    auto STS = [&](int s) {
        #pragma unroll
        for (int i = 0; i < 4; i++) {
            int idx = tid + i * 256;
            int row = idx >> 3;
            int c4  = idx & 7;
            uint4 ua = make_uint4(f2tf32(ra[i].x), f2tf32(ra[i].y),
                                  f2tf32(ra[i].z), f2tf32(ra[i].w));
            uint4 ub = make_uint4(f2tf32(rb[i].x), f2tf32(rb[i].y),
                                  f2tf32(rb[i].z), f2tf32(rb[i].w));
            *(uint4*)(As + s * BM * LDT + row * LDT + c4 * 4) = ua;
            *(uint4*)(Bs + s * BN * LDT + row * LDT + c4 * 4) = ub;
        }
    };

    auto COMP = [&](int s) {
        const unsigned* Au = As + s * BM * LDT;
        const unsigned* Bu = Bs + s * BN * LDT;
        #pragma unroll
        for (int kk = 0; kk < BK; kk += 8) {
            unsigned af[4][4], bf[4][2];
            #pragma unroll
            for (int mt = 0; mt < 4; mt++) {
                int r = wm + mt * 16 + (lane >> 2);
                int c = kk + (lane & 3);
                af[mt][0] = Au[r * LDT + c];
                af[mt][1] = Au[(r + 8) * LDT + c];
                af[mt][2] = Au[r * LDT + c + 4];
                af[mt][3] = Au[(r + 8) * LDT + c + 4];
            }
            #pragma unroll
            for (int nt = 0; nt < 4; nt++) {
                int r = wn + nt * 8 + (lane >> 2);
                int c = kk + (lane & 3);
                bf[nt][0] = Bu[r * LDT + c];
                bf[nt][1] = Bu[r * LDT + c + 4];
            }
            #pragma unroll
            for (int mt = 0; mt < 4; mt++)
                #pragma unroll
                for (int nt = 0; nt < 4; nt++)
                    asm volatile(
                        "mma.sync.aligned.m16n8k8.row.col.f32.tf32.tf32.f32 "
                        "{%0,%1,%2,%3}, {%4,%5,%6,%7}, {%8,%9}, {%0,%1,%2,%3};\n"
                        : "+f"(acc[mt][nt][0]), "+f"(acc[mt][nt][1]),
                          "+f"(acc[mt][nt][2]), "+f"(acc[mt][nt][3])
                        : "r"(af[mt][0]), "r"(af[mt][1]),
                          "r"(af[mt][2]), "r"(af[mt][3]),
                          "r"(bf[nt][0]), "r"(bf[nt][1]));
        }
    };

    LDG(0);
    STS(0);
    __syncthreads();
    for (int kt = 0; kt < NKT; kt++) {
        const int s = kt & 1;
        if (kt + 1 < NKT) LDG(kt + 1);
        COMP(s);
        if (kt + 1 < NKT) {
            STS(s ^ 1);
            __syncthreads();
        }
    }

    // epilogue: raw gates -> g_gates[z]
    float* gout = &g_gates[z][0][0];
    #pragma unroll
    for (int mt = 0; mt < 4; mt++)
        #pragma unroll
        for (int nt = 0; nt < 4; nt++) {
            int row = bm + wm + mt * 16 + (lane >> 2);
            int col = bn + wn + nt * 8 + (lane & 3) * 2;
            *(float2*)(gout + (size_t)row * G4 + col) =
                make_float2(acc[mt][nt][0], acc[mt][nt][1]);
            *(float2*)(gout + (size_t)(row + 8) * G4 + col) =
                make_float2(acc[mt][nt][2], acc[mt][nt][3]);
        }
}

// ---------------- elementwise LSTM cell update ------------------------------
__global__ void lstm_update(const float* __restrict__ bih, const float* __restrict__ bhh,
                            int layer, float* __restrict__ out, int step)
{
    int idx = blockIdx.x * blockDim.x + threadIdx.x;   // 0 .. 2*1024*256-1
    int cell = idx >> 18;
    int r = idx & 262143;
    int b = r >> 8;
    int j = r & 255;

    const float* g  = &g_gates[cell][b][0];
    const float* bi = bih + cell * G4;
    const float* bh = bhh + cell * G4;

    float gi = g[j]       + bi[j]       + bh[j];
    float gf = g[j + 256] + bi[j + 256] + bh[j + 256];
    float gc = g[j + 512] + bi[j + 512] + bh[j + 512];
    float go = g[j + 768] + bi[j + 768] + bh[j + 768];

    float i_ = 1.f / (1.f + expf(-gi));
    float f_ = 1.f / (1.f + expf(-gf));
    float gg = tanhf(gc);
    float o_ = 1.f / (1.f + expf(-go));

    int hc = layer * 2 + cell;
    float c = f_ * g_c[hc][b][j] + i_ * gg;
    float h = o_ * tanhf(c);
    g_c[hc][b][j] = c;
    g_h[hc][b][j] = h;

    if (layer == 0) {
        g_x1[b][cell * HID + j] = h;
    } else {
        g_y[b][cell * HID + j] = h;
        out[(size_t)b * (NSTEPS * 512) + (size_t)step * 512 + cell * HID + j] = h;
    }
}

// ---------------- init: code -> (h0, c0); zero feedback input ---------------
__global__ void lstm_init(const float* __restrict__ code)
{
    int idx = blockIdx.x * blockDim.x + threadIdx.x;
    if (idx < BATCH * 2048) {
        int b = idx >> 11;
        int t = idx & 2047;
        float v = code[idx];
        int l = (t >> 8) & 3;
        int j = t & 255;
        if (t < 1024) g_h[l][b][j] = v;
        else          g_c[l][b][j] = v;
    } else {
        int r = idx - BATCH * 2048;
        if (r < BATCH * 512) (&g_y[0][0])[r] = 0.f;
    }
}

// ---------------- launch ----------------------------------------------------
extern "C" void kernel_launch(void* const* d_in, const int* in_sizes, int n_in,
                              void* d_out, int out_size)
{
    const float* code = (const float*)d_in[0];
    // d_in[1] = x : unused by the reference computation
    const float* Wih0 = (const float*)d_in[2];
    const float* Whh0 = (const float*)d_in[3];
    const float* bih0 = (const float*)d_in[4];
    const float* bhh0 = (const float*)d_in[5];
    const float* Wih1 = (const float*)d_in[6];
    const float* Whh1 = (const float*)d_in[7];
    const float* bih1 = (const float*)d_in[8];
    const float* bhh1 = (const float*)d_in[9];
    float* out = (float*)d_out;

    const int smem_bytes = 2 * 2 * 128 * LDT * 4;   // 73728 B
    cudaFuncSetAttribute(lstm_gemm, cudaFuncAttributeMaxDynamicSharedMemorySize,
                         smem_bytes);

    lstm_init<<<(BATCH * 2048 + BATCH * 512) / 256, 256>>>(code);

    dim3 gg(8, 8, 2);
    for (int s = 0; s < NSTEPS; s++) {
        lstm_gemm<<<gg, 256, smem_bytes>>>(0, Wih0, Whh0);
        lstm_update<<<2048, 256>>>(bih0, bhh0, 0, out, s);
        lstm_gemm<<<gg, 256, smem_bytes>>>(1, Wih1, Whh1);
        lstm_update<<<2048, 256>>>(bih1, bhh1, 1, out, s);
    }
}

// round 8
// speedup vs baseline: 1.2655x; 1.2655x over previous
#include <cuda_runtime.h>
#include <math.h>
#include <stdint.h>

#define HID     256
#define NSTEPS  52
#define BATCH   1024

// ---------------- persistent state (device globals; no allocation) ----------
__device__ float g_h[4][BATCH][HID];      // [l0f,l0b,l1f,l1b] (tf32-rounded)
__device__ float g_c[4][BATCH][HID];      // full fp32 cell state
__device__ float g_y [BATCH][512];        // layer-0 input (prev y, tf32-rounded)
__device__ float g_x1[BATCH][512];        // layer-1 input (concat h, tf32-rounded)
__device__ float g_Wp[4][1024][768];      // packed weights [lz][j*4+gate][k], tf32-rounded
__device__ float g_bias[4][1024];         // bih+bhh, packed row order j*4+gate

// ---------------- helpers ---------------------------------------------------
__device__ __forceinline__ unsigned f2tf32(float x) {
    unsigned u;
    asm("cvt.rna.tf32.f32 %0, %1;" : "=r"(u) : "f"(x));
    return u;
}
__device__ __forceinline__ float tf32r(float x) { return __uint_as_float(f2tf32(x)); }

__device__ __forceinline__ uint32_t smem_u32(const void* p) {
    uint32_t a;
    asm("{ .reg .u64 t; cvta.to.shared.u64 t, %1; cvt.u32.u64 %0, t; }" : "=r"(a) : "l"(p));
    return a;
}
__device__ __forceinline__ float sigf(float x) { return 1.f / (1.f + __expf(-x)); }

#define STAGEB  32768          // one pipeline stage: A tile 16KB + B tile 16KB
#define NCHUNK  24             // K=768 in chunks of 32
#define GSTRIDE 132            // epilogue gate smem row stride (floats), padded

// ---------------- fused GEMM + LSTM cell step kernel ------------------------
// grid (8, 8, 2): x = j-tile (32 hidden units -> 128 packed gate rows),
//                 y = batch tile (128 rows), z = direction
__global__ void __launch_bounds__(256, 1)
lstm_step(int layer, float* __restrict__ out, int step)
{
    extern __shared__ char smem[];
    const uint32_t sb    = smem_u32(smem);
    const uint32_t base0 = (sb + 1023u) & ~1023u;   // 1024-aligned tile base

    const int tid  = threadIdx.x;
    const int lane = tid & 31;
    const int warp = tid >> 5;
    const int wm   = (warp >> 2) * 64;              // warp row offset (batch)
    const int wn   = (warp & 3) * 32;               // warp col offset (gates)
    const int z    = blockIdx.z;
    const int lz   = layer * 2 + z;
    const int n0   = blockIdx.x * 128;              // packed gate-row tile offset
    const int j0   = blockIdx.x * 32;               // hidden-unit tile offset
    const int row0 = blockIdx.y * 128;              // batch tile offset

    const float* inp  = layer ? &g_x1[0][0] : &g_y[0][0];
    const float* hsrc = &g_h[lz][0][0];
    const float* W    = &g_Wp[lz][0][0];

    float acc[4][4][4];
    #pragma unroll
    for (int a = 0; a < 4; a++)
        #pragma unroll
        for (int b = 0; b < 4; b++)
            #pragma unroll
            for (int c = 0; c < 4; c++) acc[a][b][c] = 0.f;

    // ---- cp.async producer: one K-chunk (32 cols) into stage kt&3 ----------
    auto LOAD = [&](int kt) {
        const int st = kt & 3;
        const int k0 = kt * 32;
        const uint32_t abase = base0 + st * STAGEB;
        #pragma unroll
        for (int i = 0; i < 4; i++) {
            int idx = tid + i * 256;        // 0..1023
            int row = idx >> 3;
            int c4  = idx & 7;
            int k   = k0 + c4 * 4;
            uint32_t off = row * 128 + c4 * 16;
            uint32_t sw  = off ^ ((off >> 3) & 0x70);
            const float* asrc = (k < 512)
                ? inp  + (size_t)(row0 + row) * 512 + k
                : hsrc + (size_t)(row0 + row) * 256 + (k - 512);
            const float* bsrc = W + (size_t)(n0 + row) * 768 + k;
            asm volatile("cp.async.cg.shared.global [%0], [%1], 16;"
                         :: "r"(abase + sw), "l"(asrc));
            asm volatile("cp.async.cg.shared.global [%0], [%1], 16;"
                         :: "r"(abase + 16384 + sw), "l"(bsrc));
        }
        asm volatile("cp.async.commit_group;" ::: "memory");
    };

    // ---- consumer: 4 k=8 slabs of mma over stage s --------------------------
    auto COMP = [&](int s) {
        const uint32_t abase = base0 + s * STAGEB;
        const uint32_t bbase = abase + 16384;
        #pragma unroll
        for (int kk = 0; kk < 32; kk += 8) {
            uint32_t af[4][4], bf[4][2];
            #pragma unroll
            for (int mt = 0; mt < 4; mt++) {
                int row = wm + mt * 16 + (lane & 15);
                uint32_t off = row * 128 + (lane >> 4) * 16 + kk * 4;
                uint32_t ad = abase + (off ^ ((off >> 3) & 0x70));
                asm volatile(
                    "ldmatrix.sync.aligned.m8n8.x4.shared.b16 {%0,%1,%2,%3}, [%4];"
                    : "=r"(af[mt][0]), "=r"(af[mt][1]),
                      "=r"(af[mt][2]), "=r"(af[mt][3])
                    : "r"(ad));
            }
            #pragma unroll
            for (int nt = 0; nt < 4; nt++) {
                int row = wn + nt * 8 + (lane & 7);
                uint32_t off = row * 128 + ((lane >> 3) & 1) * 16 + kk * 4;
                uint32_t bd = bbase + (off ^ ((off >> 3) & 0x70));
                asm volatile(
                    "ldmatrix.sync.aligned.m8n8.x2.shared.b16 {%0,%1}, [%2];"
                    : "=r"(bf[nt][0]), "=r"(bf[nt][1])
                    : "r"(bd));
            }
            #pragma unroll
            for (int mt = 0; mt < 4; mt++)
                #pragma unroll
                for (int nt = 0; nt < 4; nt++)
                    asm volatile(
                        "mma.sync.aligned.m16n8k8.row.col.f32.tf32.tf32.f32 "
                        "{%0,%1,%2,%3}, {%4,%5,%6,%7}, {%8,%9}, {%0,%1,%2,%3};\n"
                        : "+f"(acc[mt][nt][0]), "+f"(acc[mt][nt][1]),
                          "+f"(acc[mt][nt][2]), "+f"(acc[mt][nt][3])
                        : "r"(af[mt][0]), "r"(af[mt][1]),
                          "r"(af[mt][2]), "r"(af[mt][3]),
                          "r"(bf[nt][0]), "r"(bf[nt][1]));
        }
    };

    // ---- 4-stage pipeline, one barrier per chunk ----------------------------
    LOAD(0); LOAD(1); LOAD(2);
    for (int kt = 0; kt < 22; kt++) {
        asm volatile("cp.async.wait_group 2;" ::: "memory");
        __syncthreads();
        if (kt + 3 < NCHUNK) LOAD(kt + 3);
        COMP(kt & 3);
    }
    asm volatile("cp.async.wait_group 1;" ::: "memory");
    __syncthreads();
    COMP(22 & 3);
    asm volatile("cp.async.wait_group 0;" ::: "memory");
    __syncthreads();
    COMP(23 & 3);

    // ---- epilogue: acc -> smem (padded), then fused cell update -------------
    // Gate smem region reuses stages 0..2 (stage 3 is the only one still being
    // read by lagging warps in COMP(23); gates occupy < 3 stages => no overlap).
    char* gptr = smem + (base0 - sb);
    #pragma unroll
    for (int mt = 0; mt < 4; mt++)
        #pragma unroll
        for (int nt = 0; nt < 4; nt++) {
            int r = wm + mt * 16 + (lane >> 2);
            int c = wn + nt * 8 + (lane & 3) * 2;
            *(float2*)(gptr + (size_t)((r * GSTRIDE + c) * 4)) =
                make_float2(acc[mt][nt][0], acc[mt][nt][1]);
            *(float2*)(gptr + (size_t)(((r + 8) * GSTRIDE + c) * 4)) =
                make_float2(acc[mt][nt][2], acc[mt][nt][3]);
        }
    __syncthreads();

    #pragma unroll
    for (int it = 0; it < 16; it++) {
        int idx = tid + it * 256;           // 0..4095
        int bl  = idx >> 5;                 // local batch row 0..127
        int jl  = idx & 31;                 // local hidden unit 0..31
        float4 g4 = *(const float4*)(gptr + (size_t)((bl * GSTRIDE + jl * 4) * 4));
        float4 bs = *(const float4*)&g_bias[lz][(j0 + jl) * 4];
        int gb = row0 + bl;
        int j  = j0 + jl;
        float cc = sigf(g4.y + bs.y) * g_c[lz][gb][j]
                 + sigf(g4.x + bs.x) * tanhf(g4.z + bs.z);
        float h  = sigf(g4.w + bs.w) * tanhf(cc);
        g_c[lz][gb][j] = cc;
        float hr = tf32r(h);
        g_h[lz][gb][j] = hr;
        if (layer == 0) {
            g_x1[gb][z * 256 + j] = hr;
        } else {
            g_y[gb][z * 256 + j] = hr;
            out[(size_t)gb * (NSTEPS * 512) + (size_t)step * 512 + z * 256 + j] = h;
        }
    }
}

// ---------------- weight/bias packing (runs once per launch) ----------------
// g_Wp[layer*2+z][j*4+gate][k] = rna_tf32( k<512 ? Wih[z][gate*256+j][k]
//                                                : Whh[z][gate*256+j][k-512] )
__global__ void pack_weights(const float* __restrict__ Wih0, const float* __restrict__ Whh0,
                             const float* __restrict__ bih0, const float* __restrict__ bhh0,
                             const float* __restrict__ Wih1, const float* __restrict__ Whh1,
                             const float* __restrict__ bih1, const float* __restrict__ bhh1)
{
    long idx = (long)blockIdx.x * 256 + threadIdx.x;   // 0 .. 4*1024*768-1
    int lz  = (int)(idx / (1024 * 768));
    int rem = (int)(idx % (1024 * 768));
    int r = rem / 768;
    int k = rem % 768;
    int layer = lz >> 1, z = lz & 1;
    int gate = r & 3, j = r >> 2;
    int n = gate * 256 + j;
    const float* Wih = layer ? Wih1 : Wih0;
    const float* Whh = layer ? Whh1 : Whh0;
    float v = (k < 512) ? Wih[((size_t)z * 1024 + n) * 512 + k]
                        : Whh[((size_t)z * 1024 + n) * 256 + (k - 512)];
    g_Wp[lz][r][k] = tf32r(v);

    if (idx < 4096) {
        int blz = (int)(idx >> 10);
        int br  = (int)(idx & 1023);
        int bl = blz >> 1, bz = blz & 1;
        int bg = br & 3, bj = br >> 2;
        const float* bih = bl ? bih1 : bih0;
        const float* bhh = bl ? bhh1 : bhh0;
        g_bias[blz][br] = bih[bz * 1024 + bg * 256 + bj] + bhh[bz * 1024 + bg * 256 + bj];
    }
}

// ---------------- init: code -> (h0, c0); zero feedback input ---------------
__global__ void lstm_init(const float* __restrict__ code)
{
    int idx = blockIdx.x * blockDim.x + threadIdx.x;
    if (idx < BATCH * 2048) {
        int b = idx >> 11;
        int t = idx & 2047;
        float v = code[idx];
        int l = (t >> 8) & 3;
        int j = t & 255;
        if (t < 1024) g_h[l][b][j] = tf32r(v);
        else          g_c[l][b][j] = v;
    } else {
        int r = idx - BATCH * 2048;
        if (r < BATCH * 512) (&g_y[0][0])[r] = 0.f;
    }
}

// ---------------- launch ----------------------------------------------------
extern "C" void kernel_launch(void* const* d_in, const int* in_sizes, int n_in,
                              void* d_out, int out_size)
{
    const float* code = (const float*)d_in[0];
    // d_in[1] = x : unused by the reference computation
    const float* Wih0 = (const float*)d_in[2];
    const float* Whh0 = (const float*)d_in[3];
    const float* bih0 = (const float*)d_in[4];
    const float* bhh0 = (const float*)d_in[5];
    const float* Wih1 = (const float*)d_in[6];
    const float* Whh1 = (const float*)d_in[7];
    const float* bih1 = (const float*)d_in[8];
    const float* bhh1 = (const float*)d_in[9];
    float* out = (float*)d_out;

    const int smem_bytes = 4 * STAGEB + 1024;   // 132096 (incl. alignment slack)
    cudaFuncSetAttribute(lstm_step, cudaFuncAttributeMaxDynamicSharedMemorySize,
                         smem_bytes);

    pack_weights<<<4 * 1024 * 768 / 256, 256>>>(Wih0, Whh0, bih0, bhh0,
                                                Wih1, Whh1, bih1, bhh1);
    lstm_init<<<(BATCH * 2048 + BATCH * 512) / 256, 256>>>(code);

    dim3 grid(8, 8, 2);
    for (int s = 0; s < NSTEPS; s++) {
        lstm_step<<<grid, 256, smem_bytes>>>(0, out, s);
        lstm_step<<<grid, 256, smem_bytes>>>(1, out, s);
    }
}

// round 10
// speedup vs baseline: 1.2908x; 1.0200x over previous
#include <cuda_runtime.h>
#include <math.h>
#include <stdint.h>

#define HID     256
#define NSTEPS  52
#define BATCH   1024

// ---------------- persistent state (device globals; no allocation) ----------
__device__ float g_hd[2][4][BATCH][HID];  // double-buffered h (tf32-rounded)
__device__ float g_c[4][BATCH][HID];      // full fp32 cell state
__device__ float g_y [BATCH][512];        // layer-0 input (prev y, tf32-rounded)
__device__ float g_x1[BATCH][512];        // layer-1 input (concat h, tf32-rounded)
__device__ float g_Wp[4][1024][768];      // packed weights [lz][j*4+gate][k], tf32
__device__ float g_bias[4][1024];         // bih+bhh, packed row order j*4+gate
__device__ unsigned g_bar[8][32];         // per-band barrier counters (128B apart)

// ---------------- helpers ---------------------------------------------------
__device__ __forceinline__ unsigned f2tf32(float x) {
    unsigned u;
    asm("cvt.rna.tf32.f32 %0, %1;" : "=r"(u) : "f"(x));
    return u;
}
__device__ __forceinline__ float tf32r(float x) { return __uint_as_float(f2tf32(x)); }

__device__ __forceinline__ uint32_t smem_u32(const void* p) {
    uint32_t a;
    asm("{ .reg .u64 t; cvta.to.shared.u64 t, %1; cvt.u32.u64 %0, t; }" : "=r"(a) : "l"(p));
    return a;
}
__device__ __forceinline__ float sigf(float x) { return 1.f / (1.f + __expf(-x)); }

#define STAGEB  32768          // one pipeline stage: A tile 16KB + B tile 16KB
#define NCHUNK  24             // K=768 in chunks of 32
#define GSTRIDE 132            // epilogue gate smem row stride (floats), padded

// ---------------- persistent fused LSTM kernel ------------------------------
// 128 CTAs (<=148 SMs -> co-resident). CTA bx: band=bx>>4 (batch rows band*128),
// sub=bx&15: n0=(sub>>1)*128 (gate-row tile), z=sub&1 (direction).
// Per step: layer0 GEMM+update, band barrier, layer1 GEMM+update, band barrier.
__global__ void __launch_bounds__(256, 1)
lstm_persist(float* __restrict__ out)
{
    extern __shared__ char smem[];
    const uint32_t sb    = smem_u32(smem);
    const uint32_t base0 = (sb + 1023u) & ~1023u;

    const int tid  = threadIdx.x;
    const int lane = tid & 31;
    const int warp = tid >> 5;
    const int wm   = (warp >> 2) * 64;
    const int wn   = (warp & 3) * 32;

    const int bx   = blockIdx.x;
    const int band = bx >> 4;
    const int sub  = bx & 15;
    const int n0   = (sub >> 1) * 128;
    const int j0   = (sub >> 1) * 32;
    const int z    = sub & 1;
    const int row0 = band * 128;

    unsigned* barptr = &g_bar[band][0];
    int phase = 0;

    // per-layer pointers (reassigned each phase; lambdas capture by ref)
    const float *inp = nullptr, *hsrc = nullptr, *W = nullptr;

    float acc[4][4][4];

    // ---- B-only prefetch for stages 0..2 (uncommitted cp.asyncs) -----------
    auto PREFB = [&](const float* Wn) {
        #pragma unroll
        for (int kt = 0; kt < 3; kt++) {
            const uint32_t bbase = base0 + kt * STAGEB + 16384;
            const int k0 = kt * 32;
            #pragma unroll
            for (int i = 0; i < 4; i++) {
                int idx = tid + i * 256;
                int row = idx >> 3;
                int c4  = idx & 7;
                uint32_t off = row * 128 + c4 * 16;
                uint32_t sw  = off ^ ((off >> 3) & 0x70);
                const float* bsrc = Wn + (size_t)(n0 + row) * 768 + k0 + c4 * 4;
                asm volatile("cp.async.cg.shared.global [%0], [%1], 16;"
                             :: "r"(bbase + sw), "l"(bsrc));
            }
        }
    };

    // ---- A-only load for stages 0..2, one commit each -----------------------
    auto LOADA = [&](int kt) {
        const uint32_t abase = base0 + kt * STAGEB;
        const int k0 = kt * 32;
        #pragma unroll
        for (int i = 0; i < 4; i++) {
            int idx = tid + i * 256;
            int row = idx >> 3;
            int c4  = idx & 7;
            int k   = k0 + c4 * 4;
            uint32_t off = row * 128 + c4 * 16;
            uint32_t sw  = off ^ ((off >> 3) & 0x70);
            const float* asrc = (k < 512)
                ? inp  + (size_t)(row0 + row) * 512 + k
                : hsrc + (size_t)(row0 + row) * 256 + (k - 512);
            asm volatile("cp.async.cg.shared.global [%0], [%1], 16;"
                         :: "r"(abase + sw), "l"(asrc));
        }
        asm volatile("cp.async.commit_group;" ::: "memory");
    };

    // ---- full A+B load for chunk kt (stage kt&3), one commit ----------------
    auto LOADAB = [&](int kt) {
        const int st = kt & 3;
        const int k0 = kt * 32;
        const uint32_t abase = base0 + st * STAGEB;
        #pragma unroll
        for (int i = 0; i < 4; i++) {
            int idx = tid + i * 256;
            int row = idx >> 3;
            int c4  = idx & 7;
            int k   = k0 + c4 * 4;
            uint32_t off = row * 128 + c4 * 16;
            uint32_t sw  = off ^ ((off >> 3) & 0x70);
            const float* asrc = (k < 512)
                ? inp  + (size_t)(row0 + row) * 512 + k
                : hsrc + (size_t)(row0 + row) * 256 + (k - 512);
            const float* bsrc = W + (size_t)(n0 + row) * 768 + k;
            asm volatile("cp.async.cg.shared.global [%0], [%1], 16;"
                         :: "r"(abase + sw), "l"(asrc));
            asm volatile("cp.async.cg.shared.global [%0], [%1], 16;"
                         :: "r"(abase + 16384 + sw), "l"(bsrc));
        }
        asm volatile("cp.async.commit_group;" ::: "memory");
    };

    // ---- fragment fetch for one k=8 slab ------------------------------------
    auto LDFRAG = [&](uint32_t abase, uint32_t bbase, int kk,
                      uint32_t (&af)[4][4], uint32_t (&bf)[4][2]) {
        #pragma unroll
        for (int mt = 0; mt < 4; mt++) {
            int row = wm + mt * 16 + (lane & 15);
            uint32_t off = row * 128 + (lane >> 4) * 16 + kk * 4;
            uint32_t ad = abase + (off ^ ((off >> 3) & 0x70));
            asm volatile(
                "ldmatrix.sync.aligned.m8n8.x4.shared.b16 {%0,%1,%2,%3}, [%4];"
                : "=r"(af[mt][0]), "=r"(af[mt][1]),
                  "=r"(af[mt][2]), "=r"(af[mt][3])
                : "r"(ad));
        }
        #pragma unroll
        for (int nt = 0; nt < 4; nt++) {
            int row = wn + nt * 8 + (lane & 7);
            uint32_t off = row * 128 + ((lane >> 3) & 1) * 16 + kk * 4;
            uint32_t bd = bbase + (off ^ ((off >> 3) & 0x70));
            asm volatile(
                "ldmatrix.sync.aligned.m8n8.x2.shared.b16 {%0,%1}, [%2];"
                : "=r"(bf[nt][0]), "=r"(bf[nt][1])
                : "r"(bd));
        }
    };

    // ---- consumer: 4 slabs, fragments double-buffered across slabs ----------
    auto COMP = [&](int s) {
        const uint32_t abase = base0 + s * STAGEB;
        const uint32_t bbase = abase + 16384;
        uint32_t af[2][4][4], bf[2][4][2];
        LDFRAG(abase, bbase, 0, af[0], bf[0]);
        #pragma unroll
        for (int sl = 0; sl < 4; sl++) {
            const int cur = sl & 1;
            if (sl < 3) LDFRAG(abase, bbase, (sl + 1) * 8, af[cur ^ 1], bf[cur ^ 1]);
            #pragma unroll
            for (int mt = 0; mt < 4; mt++)
                #pragma unroll
                for (int nt = 0; nt < 4; nt++)
                    asm volatile(
                        "mma.sync.aligned.m16n8k8.row.col.f32.tf32.tf32.f32 "
                        "{%0,%1,%2,%3}, {%4,%5,%6,%7}, {%8,%9}, {%0,%1,%2,%3};\n"
                        : "+f"(acc[mt][nt][0]), "+f"(acc[mt][nt][1]),
                          "+f"(acc[mt][nt][2]), "+f"(acc[mt][nt][3])
                        : "r"(af[cur][mt][0]), "r"(af[cur][mt][1]),
                          "r"(af[cur][mt][2]), "r"(af[cur][mt][3]),
                          "r"(bf[cur][nt][0]), "r"(bf[cur][nt][1]));
        }
    };

    // ---- initial weight prefetch for (s=0, layer=0) -------------------------
    PREFB(&g_Wp[z][0][0]);

    for (int s = 0; s < NSTEPS; s++) {
        #pragma unroll 1
        for (int layer = 0; layer < 2; layer++) {
            const int lz   = layer * 2 + z;
            const int hsel = s & 1;
            inp  = layer ? &g_x1[0][0] : &g_y[0][0];
            hsrc = &g_hd[hsel][lz][0][0];
            W    = &g_Wp[lz][0][0];

            #pragma unroll
            for (int a = 0; a < 4; a++)
                #pragma unroll
                for (int b = 0; b < 4; b++)
                    #pragma unroll
                    for (int c = 0; c < 4; c++) acc[a][b][c] = 0.f;

            // stage 0..2 A loads; group 1 also carries the prefetched B tiles
            LOADA(0); LOADA(1); LOADA(2);

            for (int kt = 0; kt < 22; kt++) {
                asm volatile("cp.async.wait_group 2;" ::: "memory");
                __syncthreads();
                if (kt + 3 < NCHUNK) LOADAB(kt + 3);
                COMP(kt & 3);
            }
            asm volatile("cp.async.wait_group 1;" ::: "memory");
            __syncthreads();
            COMP(22 & 3);
            asm volatile("cp.async.wait_group 0;" ::: "memory");
            __syncthreads();
            COMP(23 & 3);

            // ---- epilogue: acc -> padded smem, fused cell update ------------
            char* gptr = smem + (base0 - sb);
            #pragma unroll
            for (int mt = 0; mt < 4; mt++)
                #pragma unroll
                for (int nt = 0; nt < 4; nt++) {
                    int r = wm + mt * 16 + (lane >> 2);
                    int c = wn + nt * 8 + (lane & 3) * 2;
                    *(float2*)(gptr + (size_t)((r * GSTRIDE + c) * 4)) =
                        make_float2(acc[mt][nt][0], acc[mt][nt][1]);
                    *(float2*)(gptr + (size_t)(((r + 8) * GSTRIDE + c) * 4)) =
                        make_float2(acc[mt][nt][2], acc[mt][nt][3]);
                }
            __syncthreads();

            #pragma unroll
            for (int it = 0; it < 16; it++) {
                int idx = tid + it * 256;
                int bl  = idx >> 5;
                int jl  = idx & 31;
                float4 g4 = *(const float4*)(gptr + (size_t)((bl * GSTRIDE + jl * 4) * 4));
                float4 bs = *(const float4*)&g_bias[lz][(j0 + jl) * 4];
                int gb = row0 + bl;
                int j  = j0 + jl;
                float cc = sigf(g4.y + bs.y) * g_c[lz][gb][j]
                         + sigf(g4.x + bs.x) * tanhf(g4.z + bs.z);
                float h  = sigf(g4.w + bs.w) * tanhf(cc);
                g_c[lz][gb][j] = cc;
                float hr = tf32r(h);
                g_hd[hsel ^ 1][lz][gb][j] = hr;
                if (layer == 0) {
                    g_x1[gb][z * 256 + j] = hr;
                } else {
                    g_y[gb][z * 256 + j] = hr;
                    out[(size_t)gb * (NSTEPS * 512) + (size_t)s * 512 + z * 256 + j] = h;
                }
            }
            __syncthreads();   // gate smem reads done before B prefetch reuses it

            // ---- prefetch next phase's weights over the barrier -------------
            const bool last = (s == NSTEPS - 1) && (layer == 1);
            if (!last) {
                const float* Wn = (layer == 0) ? &g_Wp[2 + z][0][0] : &g_Wp[z][0][0];
                PREFB(Wn);

                // ---- band barrier (16 CTAs), monotonic counter --------------
                phase++;
                if (tid == 0) {
                    unsigned tgt = (unsigned)phase * 16u;
                    unsigned tmp;
                    asm volatile("atom.release.gpu.global.add.u32 %0, [%1], 1;"
                                 : "=r"(tmp) : "l"(barptr) : "memory");
                    unsigned v;
                    do {
                        asm volatile("ld.acquire.gpu.global.u32 %0, [%1];"
                                     : "=r"(v) : "l"(barptr) : "memory");
                        if (v < tgt) __nanosleep(64);
                    } while (v < tgt);
                }
                __syncthreads();
            }
        }
    }
}

// ---------------- weight/bias packing (runs once per launch) ----------------
__global__ void pack_weights(const float* __restrict__ Wih0, const float* __restrict__ Whh0,
                             const float* __restrict__ bih0, const float* __restrict__ bhh0,
                             const float* __restrict__ Wih1, const float* __restrict__ Whh1,
                             const float* __restrict__ bih1, const float* __restrict__ bhh1)
{
    long idx = (long)blockIdx.x * 256 + threadIdx.x;   // 0 .. 4*1024*768-1
    int lz  = (int)(idx / (1024 * 768));
    int rem = (int)(idx % (1024 * 768));
    int r = rem / 768;
    int k = rem % 768;
    int layer = lz >> 1, z = lz & 1;
    int gate = r & 3, j = r >> 2;
    int n = gate * 256 + j;
    const float* Wih = layer ? Wih1 : Wih0;
    const float* Whh = layer ? Whh1 : Whh0;
    float v = (k < 512) ? Wih[((size_t)z * 1024 + n) * 512 + k]
                        : Whh[((size_t)z * 1024 + n) * 256 + (k - 512)];
    g_Wp[lz][r][k] = tf32r(v);

    if (idx < 4096) {
        int blz = (int)(idx >> 10);
        int br  = (int)(idx & 1023);
        int bl = blz >> 1, bz = blz & 1;
        int bg = br & 3, bj = br >> 2;
        const float* bih = bl ? bih1 : bih0;
        const float* bhh = bl ? bhh1 : bhh0;
        g_bias[blz][br] = bih[bz * 1024 + bg * 256 + bj] + bhh[bz * 1024 + bg * 256 + bj];
    }
}

// ---------------- init: code -> (h0, c0); zero feedback; reset barriers -----
__global__ void lstm_init(const float* __restrict__ code)
{
    int idx = blockIdx.x * blockDim.x + threadIdx.x;
    if (idx < BATCH * 2048) {
        int b = idx >> 11;
        int t = idx & 2047;
        float v = code[idx];
        int l = (t >> 8) & 3;
        int j = t & 255;
        if (t < 1024) g_hd[0][l][b][j] = tf32r(v);
        else          g_c[l][b][j] = v;
    } else {
        int r = idx - BATCH * 2048;
        if (r < BATCH * 512) (&g_y[0][0])[r] = 0.f;
    }
    if (idx < 8) g_bar[idx][0] = 0u;
}

// ---------------- launch ----------------------------------------------------
extern "C" void kernel_launch(void* const* d_in, const int* in_sizes, int n_in,
                              void* d_out, int out_size)
{
    const float* code = (const float*)d_in[0];
    // d_in[1] = x : unused by the reference computation
    const float* Wih0 = (const float*)d_in[2];
    const float* Whh0 = (const float*)d_in[3];
    const float* bih0 = (const float*)d_in[4];
    const float* bhh0 = (const float*)d_in[5];
    const float* Wih1 = (const float*)d_in[6];
    const float* Whh1 = (const float*)d_in[7];
    const float* bih1 = (const float*)d_in[8];
    const float* bhh1 = (const float*)d_in[9];
    float* out = (float*)d_out;

    const int smem_bytes = 4 * STAGEB + 1024;   // 132096
    cudaFuncSetAttribute(lstm_persist, cudaFuncAttributeMaxDynamicSharedMemorySize,
                         smem_bytes);

    pack_weights<<<4 * 1024 * 768 / 256, 256>>>(Wih0, Whh0, bih0, bhh0,
                                                Wih1, Whh1, bih1, bhh1);
    lstm_init<<<(BATCH * 2048 + BATCH * 512) / 256, 256>>>(code);

    lstm_persist<<<128, 256, smem_bytes>>>(out);
}

// round 12
// speedup vs baseline: 1.4022x; 1.0863x over previous
#include <cuda_runtime.h>
#include <math.h>
#include <stdint.h>

#define HID     256
#define NSTEPS  52
#define BATCH   1024

// ---------------- persistent state (device globals; no allocation) ----------
__device__ float g_hd[2][4][BATCH][HID];  // double-buffered h (tf32-rounded)
__device__ float g_c[4][BATCH][HID];      // full fp32 cell state
__device__ float g_y [BATCH][512];        // layer-0 input (prev y, tf32-rounded)
__device__ float g_x1[BATCH][512];        // layer-1 input (concat h, tf32-rounded)
__device__ float g_Wp[4][1024][768];      // packed weights [lz][j*4+gate][k], tf32
__device__ float g_bias[4][1024];         // bih+bhh, packed row order j*4+gate
__device__ unsigned g_bar[8][32];         // per-band barrier counters (128B apart)

// ---------------- helpers ---------------------------------------------------
__device__ __forceinline__ unsigned f2tf32(float x) {
    unsigned u;
    asm("cvt.rna.tf32.f32 %0, %1;" : "=r"(u) : "f"(x));
    return u;
}
__device__ __forceinline__ float tf32r(float x) { return __uint_as_float(f2tf32(x)); }

__device__ __forceinline__ uint32_t smem_u32(const void* p) {
    uint32_t a;
    asm("{ .reg .u64 t; cvta.to.shared.u64 t, %1; cvt.u32.u64 %0, t; }" : "=r"(a) : "l"(p));
    return a;
}
__device__ __forceinline__ float sigf(float x) { return 1.f / (1.f + __expf(-x)); }

#define NTHREADS 512
#define STAGEB  32768          // one pipeline stage: A tile 16KB + B tile 16KB
#define NCHUNK  24             // K=768 in chunks of 32
#define GSTRIDE 132            // epilogue gate smem row stride (floats), padded

// ---------------- persistent fused LSTM kernel ------------------------------
// 128 CTAs (<=148 SMs -> co-resident). CTA bx: band=bx>>4 (batch rows band*128),
// sub=bx&15: n0=(sub>>1)*128 (gate-row tile), z=sub&1 (direction).
// 16 warps in a 4x4 layout; each warp owns a 32x32 output tile.
__global__ void __launch_bounds__(NTHREADS, 1)
lstm_persist(float* __restrict__ out)
{
    extern __shared__ char smem[];
    const uint32_t sb    = smem_u32(smem);
    const uint32_t base0 = (sb + 1023u) & ~1023u;

    const int tid  = threadIdx.x;
    const int lane = tid & 31;
    const int warp = tid >> 5;
    const int wm   = (warp >> 2) * 32;      // warp row offset (batch), 4 groups
    const int wn   = (warp & 3) * 32;       // warp col offset (gates), 4 groups

    const int bx   = blockIdx.x;
    const int band = bx >> 4;
    const int sub  = bx & 15;
    const int n0   = (sub >> 1) * 128;
    const int j0   = (sub >> 1) * 32;
    const int z    = sub & 1;
    const int row0 = band * 128;

    unsigned* barptr = &g_bar[band][0];
    int phase = 0;

    const float *inp = nullptr, *hsrc = nullptr, *W = nullptr;

    float acc[2][4][4];   // [mt][nt][frag] for the 32x32 warp tile

    // ---- B-only prefetch for stages 0..2 (uncommitted cp.asyncs) -----------
    auto PREFB = [&](const float* Wn) {
        #pragma unroll
        for (int kt = 0; kt < 3; kt++) {
            const uint32_t bbase = base0 + kt * STAGEB + 16384;
            const int k0 = kt * 32;
            #pragma unroll
            for (int i = 0; i < 2; i++) {
                int idx = tid + i * NTHREADS;       // 0..1023
                int row = idx >> 3;
                int c4  = idx & 7;
                uint32_t off = row * 128 + c4 * 16;
                uint32_t sw  = off ^ ((off >> 3) & 0x70);
                const float* bsrc = Wn + (size_t)(n0 + row) * 768 + k0 + c4 * 4;
                asm volatile("cp.async.cg.shared.global [%0], [%1], 16;"
                             :: "r"(bbase + sw), "l"(bsrc));
            }
        }
    };

    // ---- A-only load for stages 0..2, one commit each -----------------------
    auto LOADA = [&](int kt) {
        const uint32_t abase = base0 + kt * STAGEB;
        const int k0 = kt * 32;
        #pragma unroll
        for (int i = 0; i < 2; i++) {
            int idx = tid + i * NTHREADS;
            int row = idx >> 3;
            int c4  = idx & 7;
            int k   = k0 + c4 * 4;
            uint32_t off = row * 128 + c4 * 16;
            uint32_t sw  = off ^ ((off >> 3) & 0x70);
            const float* asrc = (k < 512)
                ? inp  + (size_t)(row0 + row) * 512 + k
                : hsrc + (size_t)(row0 + row) * 256 + (k - 512);
            asm volatile("cp.async.cg.shared.global [%0], [%1], 16;"
                         :: "r"(abase + sw), "l"(asrc));
        }
        asm volatile("cp.async.commit_group;" ::: "memory");
    };

    // ---- full A+B load for chunk kt (stage kt&3), one commit ----------------
    auto LOADAB = [&](int kt) {
        const int st = kt & 3;
        const int k0 = kt * 32;
        const uint32_t abase = base0 + st * STAGEB;
        #pragma unroll
        for (int i = 0; i < 2; i++) {
            int idx = tid + i * NTHREADS;
            int row = idx >> 3;
            int c4  = idx & 7;
            int k   = k0 + c4 * 4;
            uint32_t off = row * 128 + c4 * 16;
            uint32_t sw  = off ^ ((off >> 3) & 0x70);
            const float* asrc = (k < 512)
                ? inp  + (size_t)(row0 + row) * 512 + k
                : hsrc + (size_t)(row0 + row) * 256 + (k - 512);
            const float* bsrc = W + (size_t)(n0 + row) * 768 + k;
            asm volatile("cp.async.cg.shared.global [%0], [%1], 16;"
                         :: "r"(abase + sw), "l"(asrc));
            asm volatile("cp.async.cg.shared.global [%0], [%1], 16;"
                         :: "r"(abase + 16384 + sw), "l"(bsrc));
        }
        asm volatile("cp.async.commit_group;" ::: "memory");
    };

    // ---- fragment fetch for one k=8 slab: 2 x4 (A) + 2 x4 (B) ---------------
    auto LDFRAG = [&](uint32_t abase, uint32_t bbase, int kk,
                      uint32_t (&af)[2][4], uint32_t (&bf)[4][2]) {
        #pragma unroll
        for (int mt = 0; mt < 2; mt++) {
            int row = wm + mt * 16 + (lane & 15);
            uint32_t off = row * 128 + (lane >> 4) * 16 + kk * 4;
            uint32_t ad = abase + (off ^ ((off >> 3) & 0x70));
            asm volatile(
                "ldmatrix.sync.aligned.m8n8.x4.shared.b16 {%0,%1,%2,%3}, [%4];"
                : "=r"(af[mt][0]), "=r"(af[mt][1]),
                  "=r"(af[mt][2]), "=r"(af[mt][3])
                : "r"(ad));
        }
        #pragma unroll
        for (int ntp = 0; ntp < 2; ntp++) {
            int row = wn + ntp * 16 + ((lane >> 4) & 1) * 8 + (lane & 7);
            uint32_t off = row * 128 + ((lane >> 3) & 1) * 16 + kk * 4;
            uint32_t bd = bbase + (off ^ ((off >> 3) & 0x70));
            asm volatile(
                "ldmatrix.sync.aligned.m8n8.x4.shared.b16 {%0,%1,%2,%3}, [%4];"
                : "=r"(bf[2 * ntp][0]), "=r"(bf[2 * ntp][1]),
                  "=r"(bf[2 * ntp + 1][0]), "=r"(bf[2 * ntp + 1][1])
                : "r"(bd));
        }
    };

    // ---- consumer: 4 slabs, fragments double-buffered across slabs ----------
    auto COMP = [&](int s) {
        const uint32_t abase = base0 + s * STAGEB;
        const uint32_t bbase = abase + 16384;
        uint32_t af[2][2][4], bf[2][4][2];
        LDFRAG(abase, bbase, 0, af[0], bf[0]);
        #pragma unroll
        for (int sl = 0; sl < 4; sl++) {
            const int cur = sl & 1;
            if (sl < 3) LDFRAG(abase, bbase, (sl + 1) * 8, af[cur ^ 1], bf[cur ^ 1]);
            #pragma unroll
            for (int mt = 0; mt < 2; mt++)
                #pragma unroll
                for (int nt = 0; nt < 4; nt++)
                    asm volatile(
                        "mma.sync.aligned.m16n8k8.row.col.f32.tf32.tf32.f32 "
                        "{%0,%1,%2,%3}, {%4,%5,%6,%7}, {%8,%9}, {%0,%1,%2,%3};\n"
                        : "+f"(acc[mt][nt][0]), "+f"(acc[mt][nt][1]),
                          "+f"(acc[mt][nt][2]), "+f"(acc[mt][nt][3])
                        : "r"(af[cur][mt][0]), "r"(af[cur][mt][1]),
                          "r"(af[cur][mt][2]), "r"(af[cur][mt][3]),
                          "r"(bf[cur][nt][0]), "r"(bf[cur][nt][1]));
        }
    };

    // ---- initial weight prefetch for (s=0, layer=0) -------------------------
    PREFB(&g_Wp[z][0][0]);

    for (int s = 0; s < NSTEPS; s++) {
        #pragma unroll 1
        for (int layer = 0; layer < 2; layer++) {
            const int lz   = layer * 2 + z;
            const int hsel = s & 1;
            inp  = layer ? &g_x1[0][0] : &g_y[0][0];
            hsrc = &g_hd[hsel][lz][0][0];
            W    = &g_Wp[lz][0][0];

            #pragma unroll
            for (int a = 0; a < 2; a++)
                #pragma unroll
                for (int b = 0; b < 4; b++)
                    #pragma unroll
                    for (int c = 0; c < 4; c++) acc[a][b][c] = 0.f;

            // stage 0..2 A loads; group 1 also carries the prefetched B tiles
            LOADA(0); LOADA(1); LOADA(2);

            for (int kt = 0; kt < 22; kt++) {
                asm volatile("cp.async.wait_group 2;" ::: "memory");
                __syncthreads();
                if (kt + 3 < NCHUNK) LOADAB(kt + 3);
                COMP(kt & 3);
            }
            asm volatile("cp.async.wait_group 1;" ::: "memory");
            __syncthreads();
            COMP(22 & 3);
            asm volatile("cp.async.wait_group 0;" ::: "memory");
            __syncthreads();
            COMP(23 & 3);

            // ---- epilogue: acc -> padded smem, fused cell update ------------
            char* gptr = smem + (base0 - sb);
            #pragma unroll
            for (int mt = 0; mt < 2; mt++)
                #pragma unroll
                for (int nt = 0; nt < 4; nt++) {
                    int r = wm + mt * 16 + (lane >> 2);
                    int c = wn + nt * 8 + (lane & 3) * 2;
                    *(float2*)(gptr + (size_t)((r * GSTRIDE + c) * 4)) =
                        make_float2(acc[mt][nt][0], acc[mt][nt][1]);
                    *(float2*)(gptr + (size_t)(((r + 8) * GSTRIDE + c) * 4)) =
                        make_float2(acc[mt][nt][2], acc[mt][nt][3]);
                }
            __syncthreads();

            #pragma unroll
            for (int it = 0; it < 8; it++) {
                int idx = tid + it * NTHREADS;      // 0..4095
                int bl  = idx >> 5;
                int jl  = idx & 31;
                float4 g4 = *(const float4*)(gptr + (size_t)((bl * GSTRIDE + jl * 4) * 4));
                float4 bs = *(const float4*)&g_bias[lz][(j0 + jl) * 4];
                int gb = row0 + bl;
                int j  = j0 + jl;
                float cc = sigf(g4.y + bs.y) * g_c[lz][gb][j]
                         + sigf(g4.x + bs.x) * tanhf(g4.z + bs.z);
                float h  = sigf(g4.w + bs.w) * tanhf(cc);
                g_c[lz][gb][j] = cc;
                float hr = tf32r(h);
                g_hd[hsel ^ 1][lz][gb][j] = hr;
                if (layer == 0) {
                    g_x1[gb][z * 256 + j] = hr;
                } else {
                    g_y[gb][z * 256 + j] = hr;
                    out[(size_t)gb * (NSTEPS * 512) + (size_t)s * 512 + z * 256 + j] = h;
                }
            }
            __syncthreads();   // gate smem reads done before B prefetch reuses it

            // ---- prefetch next phase's weights over the barrier -------------
            const bool last = (s == NSTEPS - 1) && (layer == 1);
            if (!last) {
                const float* Wn = (layer == 0) ? &g_Wp[2 + z][0][0] : &g_Wp[z][0][0];
                PREFB(Wn);

                // ---- band barrier (16 CTAs), monotonic counter --------------
                phase++;
                if (tid == 0) {
                    unsigned tgt = (unsigned)phase * 16u;
                    unsigned tmp;
                    asm volatile("atom.release.gpu.global.add.u32 %0, [%1], 1;"
                                 : "=r"(tmp) : "l"(barptr) : "memory");
                    unsigned v;
                    do {
                        asm volatile("ld.acquire.gpu.global.u32 %0, [%1];"
                                     : "=r"(v) : "l"(barptr) : "memory");
                        if (v < tgt) __nanosleep(64);
                    } while (v < tgt);
                }
                __syncthreads();
            }
        }
    }
}

// ---------------- weight/bias packing (runs once per launch) ----------------
__global__ void pack_weights(const float* __restrict__ Wih0, const float* __restrict__ Whh0,
                             const float* __restrict__ bih0, const float* __restrict__ bhh0,
                             const float* __restrict__ Wih1, const float* __restrict__ Whh1,
                             const float* __restrict__ bih1, const float* __restrict__ bhh1)
{
    long idx = (long)blockIdx.x * 256 + threadIdx.x;   // 0 .. 4*1024*768-1
    int lz  = (int)(idx / (1024 * 768));
    int rem = (int)(idx % (1024 * 768));
    int r = rem / 768;
    int k = rem % 768;
    int layer = lz >> 1, z = lz & 1;
    int gate = r & 3, j = r >> 2;
    int n = gate * 256 + j;
    const float* Wih = layer ? Wih1 : Wih0;
    const float* Whh = layer ? Whh1 : Whh0;
    float v = (k < 512) ? Wih[((size_t)z * 1024 + n) * 512 + k]
                        : Whh[((size_t)z * 1024 + n) * 256 + (k - 512)];
    g_Wp[lz][r][k] = tf32r(v);

    if (idx < 4096) {
        int blz = (int)(idx >> 10);
        int br  = (int)(idx & 1023);
        int bl = blz >> 1, bz = blz & 1;
        int bg = br & 3, bj = br >> 2;
        const float* bih = bl ? bih1 : bih0;
        const float* bhh = bl ? bhh1 : bhh0;
        g_bias[blz][br] = bih[bz * 1024 + bg * 256 + bj] + bhh[bz * 1024 + bg * 256 + bj];
    }
}

// ---------------- init: code -> (h0, c0); zero feedback; reset barriers -----
__global__ void lstm_init(const float* __restrict__ code)
{
    int idx = blockIdx.x * blockDim.x + threadIdx.x;
    if (idx < BATCH * 2048) {
        int b = idx >> 11;
        int t = idx & 2047;
        float v = code[idx];
        int l = (t >> 8) & 3;
        int j = t & 255;
        if (t < 1024) g_hd[0][l][b][j] = tf32r(v);
        else          g_c[l][b][j] = v;
    } else {
        int r = idx - BATCH * 2048;
        if (r < BATCH * 512) (&g_y[0][0])[r] = 0.f;
    }
    if (idx < 8) g_bar[idx][0] = 0u;
}

// ---------------- launch ----------------------------------------------------
extern "C" void kernel_launch(void* const* d_in, const int* in_sizes, int n_in,
                              void* d_out, int out_size)
{
    const float* code = (const float*)d_in[0];
    // d_in[1] = x : unused by the reference computation
    const float* Wih0 = (const float*)d_in[2];
    const float* Whh0 = (const float*)d_in[3];
    const float* bih0 = (const float*)d_in[4];
    const float* bhh0 = (const float*)d_in[5];
    const float* Wih1 = (const float*)d_in[6];
    const float* Whh1 = (const float*)d_in[7];
    const float* bih1 = (const float*)d_in[8];
    const float* bhh1 = (const float*)d_in[9];
    float* out = (float*)d_out;

    const int smem_bytes = 4 * STAGEB + 1024;   // 132096
    cudaFuncSetAttribute(lstm_persist, cudaFuncAttributeMaxDynamicSharedMemorySize,
                         smem_bytes);

    pack_weights<<<4 * 1024 * 768 / 256, 256>>>(Wih0, Whh0, bih0, bhh0,
                                                Wih1, Whh1, bih1, bhh1);
    lstm_init<<<(BATCH * 2048 + BATCH * 512) / 256, 256>>>(code);

    lstm_persist<<<128, NTHREADS, smem_bytes>>>(out);
}